// round 16
// baseline (speedup 1.0000x reference)
#include <cuda_runtime.h>
#include <cuda_fp16.h>
#include <stdint.h>

// Hopfield layer via warp-level fp16 mma.sync (sm_100 target, no tcgen05).
// R16: R13/R15 inner loop unchanged; overhead cuts only:
//  - step-1 Q (fp32 R) converted in-kernel during prologue (R tohalf deleted)
//  - 3-buffer KV ring -> ONE __syncthreads per tile (was 2)
// fp16 operands, fp32 accum, C folded into Q, f16x2 packing, ones-column MMA
// row sums, unnormalized softmax, normalize at end.

#define DM 512
#define QT 256
#define ST 64
#define THREADS 256

// dynamic smem: 3 KV buffers (8KB each) + Q tile (32KB)
#define KBUF(i)  ((uint32_t)(i) * 8192u)
#define QB0 24576
#define SMEM_TOTAL 57344

#define NELEM (2u * 2048u * 512u)
__device__ __half gYh[NELEM];
__device__ __half gTh[NELEM];

static __device__ __forceinline__ uint32_t s2u(const void* p) {
    uint32_t a;
    asm("{ .reg .u64 t; cvta.to.shared.u64 t, %1; cvt.u32.u64 %0, t; }"
        : "=r"(a) : "l"(p));
    return a;
}
static __device__ __forceinline__ uint32_t off(int row, int chunk) {
    return (uint32_t)(row * 128 + ((chunk ^ (row & 7)) << 4));
}
static __device__ __forceinline__ float ex2f_(float x) {
    float r; asm("ex2.approx.ftz.f32 %0, %1;" : "=f"(r) : "f"(x)); return r;
}
static __device__ __forceinline__ uint32_t packh2(float lo, float hi) {
    uint32_t r;
    asm("cvt.rn.f16x2.f32 %0, %1, %2;" : "=r"(r) : "f"(hi), "f"(lo));
    return r;
}

static __device__ __forceinline__ void mma_f16(float c[4], const uint32_t a[4],
                                               const uint32_t b[2]) {
    asm("mma.sync.aligned.m16n8k16.row.col.f32.f16.f16.f32 "
        "{%0,%1,%2,%3}, {%4,%5,%6,%7}, {%8,%9}, {%0,%1,%2,%3};"
        : "+f"(c[0]), "+f"(c[1]), "+f"(c[2]), "+f"(c[3])
        : "r"(a[0]), "r"(a[1]), "r"(a[2]), "r"(a[3]), "r"(b[0]), "r"(b[1]));
}
#define LDSM4(r, a) \
    asm volatile("ldmatrix.sync.aligned.m8n8.x4.shared.b16 {%0,%1,%2,%3}, [%4];" \
        : "=r"((r)[0]), "=r"((r)[1]), "=r"((r)[2]), "=r"((r)[3]) : "r"(a))
#define LDSM4T(r, a) \
    asm volatile("ldmatrix.sync.aligned.m8n8.x4.trans.shared.b16 {%0,%1,%2,%3}, [%4];" \
        : "=r"((r)[0]), "=r"((r)[1]), "=r"((r)[2]), "=r"((r)[3]) : "r"(a))
#define CPA(dst, src) \
    asm volatile("cp.async.cg.shared.global [%0], [%1], 16;" :: "r"(dst), "l"(src))
#define CPC() asm volatile("cp.async.commit_group;" ::: "memory")
#define CPW(n) asm volatile("cp.async.wait_group %0;" :: "n"(n) : "memory")
#define STS128(a, r0, r1, r2, r3) \
    asm volatile("st.shared.v4.b32 [%0], {%1,%2,%3,%4};" \
        :: "r"(a), "r"(r0), "r"(r1), "r"(r2), "r"(r3) : "memory")

__global__ void tohalf(const float4* __restrict__ src, uint2* __restrict__ dst,
                       int n4, float scale)
{
    int i = blockIdx.x * blockDim.x + threadIdx.x;
    if (i < n4) {
        float4 x = src[i];
        dst[i] = make_uint2(packh2(x.x * scale, x.y * scale),
                            packh2(x.z * scale, x.w * scale));
    }
}

__global__ __launch_bounds__(THREADS, 1)
void hopfield_mma(const float* __restrict__ Qf, const __half* __restrict__ Qh,
                  const __half* __restrict__ Km,
                  float* __restrict__ outF, __half* __restrict__ outH,
                  int L, int S, float qscale, float outScale)
{
    extern __shared__ __align__(16) uint8_t smem[];
    const uint32_t sb = s2u(smem);
    const uint32_t qB = sb + QB0;

    const int tid = threadIdx.x;
    const int wid = tid >> 5;
    const int lane = tid & 31;
    const int h = blockIdx.y, b = blockIdx.z;

    const uint32_t ones2[2] = { 0x3C003C00u, 0x3C003C00u };   // fp16 {1,1}

    // ---- stage full Q tile (256 rows x 64 cols fp16 = 32KB) ----
    if (Qf) {
        // step 1: fp32 source, convert (scale folded) in-kernel
        const float* qg = Qf + ((size_t)b * L + (size_t)blockIdx.x * QT) * DM + h * 64;
        int c8 = tid & 7, r0 = tid >> 3;   // c8: 8-float chunk, r0: 0..31
#pragma unroll
        for (int i = 0; i < 8; i++) {
            int row = r0 + i * 32;         // 0..255
            const float4* p = (const float4*)(qg + (size_t)row * DM + c8 * 8);
            float4 a = p[0], bb = p[1];
            STS128(qB + off(row, c8),
                   packh2(a.x * qscale, a.y * qscale),
                   packh2(a.z * qscale, a.w * qscale),
                   packh2(bb.x * qscale, bb.y * qscale),
                   packh2(bb.z * qscale, bb.w * qscale));
        }
    } else {
        // step 2: fp16 source (tmp, scale already folded)
        const __half* qg = Qh + ((size_t)b * L + (size_t)blockIdx.x * QT) * DM + h * 64;
        int c = tid & 7, r0 = tid >> 3;
#pragma unroll
        for (int i = 0; i < 8; i++) {
            int row = r0 + i * 32;
            CPA(qB + off(row, c), (const char*)(qg + (size_t)row * DM) + c * 16);
        }
        CPC(); CPW(0);
    }
    __syncthreads();

    const __half* kg = Km + (size_t)b * S * DM + h * 64;
    const int NT = S / ST;   // 32

    // prefetch tiles 0, 1 into ring buffers 0, 1 (one group each)
    {
        int c = tid & 7, r0 = tid >> 3;
#pragma unroll
        for (int pf = 0; pf < 2; pf++) {
            uint32_t bh = sb + KBUF(pf);
            const char* hs = (const char*)(kg + (size_t)pf * ST * DM);
#pragma unroll
            for (int i = 0; i < 2; i++) {
                int row = r0 + i * 32;
                CPA(bh + off(row, c), hs + (size_t)row * DM * 2 + c * 16);
            }
            CPC();
        }
    }

    // per-warp A fragments: 2 row-tiles of 16x64; warp w owns rows 32w..32w+31
    uint32_t qf[2][4][4];
#pragma unroll
    for (int rt = 0; rt < 2; rt++) {
        int gr = 32 * wid + 16 * rt + (lane & 15);
#pragma unroll
        for (int t = 0; t < 4; t++) {
            int ch = 2 * t + (lane >> 4);
            LDSM4(qf[rt][t], qB + off(gr, ch));
        }
    }

    float oacc[2][8][4];
#pragma unroll
    for (int rt = 0; rt < 2; rt++)
#pragma unroll
        for (int j = 0; j < 8; j++)
#pragma unroll
            for (int i = 0; i < 4; i++) oacc[rt][j][i] = 0.f;
    float lacc[2][4] = {{0.f, 0.f, 0.f, 0.f}, {0.f, 0.f, 0.f, 0.f}};

    for (int t = 0; t < NT; t++) {
        CPW(1);                 // this thread's tile-t group complete
        __syncthreads();        // publishes tile t; also: all warps done with t-1
        const uint32_t kb = sb + KBUF(t % 3);

        // ---- process tile in two 32-key halves (bounds live registers) ----
#pragma unroll
        for (int half = 0; half < 2; half++) {
            // GEMM1-half: sc[rt][4 n-blocks][4] = Qscaled x K^T (scores * C)
            float sc[2][4][4];
#pragma unroll
            for (int rt = 0; rt < 2; rt++)
#pragma unroll
                for (int j = 0; j < 4; j++)
#pragma unroll
                    for (int i = 0; i < 4; i++) sc[rt][j][i] = 0.f;

#pragma unroll
            for (int j = 0; j < 4; j++) {
                int row = 32 * half + 8 * j + (lane & 7);
                uint32_t bh[8];
                LDSM4(bh + 0, kb + off(row, (lane >> 3)));
                LDSM4(bh + 4, kb + off(row, 4 + (lane >> 3)));
#pragma unroll
                for (int t4 = 0; t4 < 4; t4++)
#pragma unroll
                    for (int rt = 0; rt < 2; rt++)
                        mma_f16(sc[rt][j], qf[rt][t4], bh + 2 * t4);
            }

            // softmax-half: p = exp2(sc) (scale pre-folded), pack via f16x2
            uint32_t ph[2][2][4];
#pragma unroll
            for (int rt = 0; rt < 2; rt++) {
#pragma unroll
                for (int kt = 0; kt < 2; kt++) {
                    ph[rt][kt][0] = packh2(ex2f_(sc[rt][2 * kt][0]),
                                           ex2f_(sc[rt][2 * kt][1]));
                    ph[rt][kt][1] = packh2(ex2f_(sc[rt][2 * kt][2]),
                                           ex2f_(sc[rt][2 * kt][3]));
                    ph[rt][kt][2] = packh2(ex2f_(sc[rt][2 * kt + 1][0]),
                                           ex2f_(sc[rt][2 * kt + 1][1]));
                    ph[rt][kt][3] = packh2(ex2f_(sc[rt][2 * kt + 1][2]),
                                           ex2f_(sc[rt][2 * kt + 1][3]));
                }
            }

            // GEMM2-half: O += P x V, l += P x ones (row sums in fp32)
#pragma unroll
            for (int kt = 0; kt < 2; kt++) {
                int row = 32 * half + 16 * kt + (lane & 7) + (lane & 8);
#pragma unroll
                for (int jp = 0; jp < 4; jp++) {
                    int ch = 2 * jp + (lane >> 4);
                    uint32_t vh[4];
                    LDSM4T(vh, kb + off(row, ch));
#pragma unroll
                    for (int rt = 0; rt < 2; rt++) {
                        mma_f16(oacc[rt][2 * jp],     ph[rt][kt], vh + 0);
                        mma_f16(oacc[rt][2 * jp + 1], ph[rt][kt], vh + 2);
                    }
                }
#pragma unroll
                for (int rt = 0; rt < 2; rt++)
                    mma_f16(lacc[rt], ph[rt][kt], ones2);
            }
        }

        // prefetch tile t+2 into ring buffer (t+2)%3 — freed at the barrier
        // above (all warps finished tile t-1 before any warp reached here)
        if (t + 2 < NT) {
            int c = tid & 7, r0 = tid >> 3;
            uint32_t bh = sb + KBUF((t + 2) % 3);
            const char* hs = (const char*)(kg + (size_t)(t + 2) * ST * DM);
#pragma unroll
            for (int i = 0; i < 2; i++) {
                int row = r0 + i * 32;
                CPA(bh + off(row, c), hs + (size_t)row * DM * 2 + c * 16);
            }
        }
        CPC();
    }

    // ---- normalize + store (lacc cols equal the row sums; no shuffles) ----
    const int r = lane >> 2, cb = (lane & 3) * 2;
#pragma unroll
    for (int rt = 0; rt < 2; rt++) {
        float inv0 = outScale / lacc[rt][0];
        float inv1 = outScale / lacc[rt][2];

        size_t base = ((size_t)b * L + (size_t)blockIdx.x * QT + 32 * wid + 16 * rt) * DM
                    + h * 64;
        if (outF) {
#pragma unroll
            for (int j = 0; j < 8; j++) {
                *(float2*)(outF + base + (size_t)r * DM + 8 * j + cb) =
                    make_float2(oacc[rt][j][0] * inv0, oacc[rt][j][1] * inv0);
                *(float2*)(outF + base + (size_t)(r + 8) * DM + 8 * j + cb) =
                    make_float2(oacc[rt][j][2] * inv1, oacc[rt][j][3] * inv1);
            }
        } else {
#pragma unroll
            for (int j = 0; j < 8; j++) {
                *(uint32_t*)(outH + base + (size_t)r * DM + 8 * j + cb) =
                    packh2(oacc[rt][j][0] * inv0, oacc[rt][j][1] * inv0);
                *(uint32_t*)(outH + base + (size_t)(r + 8) * DM + 8 * j + cb) =
                    packh2(oacc[rt][j][2] * inv1, oacc[rt][j][3] * inv1);
            }
        }
    }
}

extern "C" void kernel_launch(void* const* d_in, const int* in_sizes, int n_in,
                              void* d_out, int out_size)
{
    const float* R = (const float*)d_in[0];
    const float* Y = (const float*)d_in[1];
    float* out = (float*)d_out;

    const int B = 2, H = 8;
    const int L = in_sizes[0] / (B * DM);   // 2048
    const int S = in_sizes[1] / (B * DM);   // 2048
    const float C = 0.125f * 1.4426950408889634f;   // scale * log2(e)

    __half *Yh, *Th;
    cudaGetSymbolAddress((void**)&Yh, gYh);
    cudaGetSymbolAddress((void**)&Th, gTh);

    cudaFuncSetAttribute(hopfield_mma, cudaFuncAttributeMaxDynamicSharedMemorySize,
                         SMEM_TOTAL);

    const int n4 = (int)(NELEM / 4);
    tohalf<<<(n4 + 255) / 256, 256>>>((const float4*)Y, (uint2*)Yh, n4, 1.0f);

    dim3 grid(L / QT, H, B);
    dim3 block(THREADS);
    // step 1: Q = R (fp32, converted in-kernel with C folded) -> fp16 tmp
    //         (tmp carries C for step 2 via outScale=C)
    hopfield_mma<<<grid, block, SMEM_TOTAL>>>(R, nullptr, Yh, nullptr, Th,
                                              L, S, C, C);
    // step 2: Q = tmp (fp16) -> fp32 out
    hopfield_mma<<<grid, block, SMEM_TOTAL>>>(nullptr, Th, Yh, out, nullptr,
                                              L, S, 0.f, 1.0f);
}

// round 17
// speedup vs baseline: 1.0641x; 1.0641x over previous
#include <cuda_runtime.h>
#include <cuda_fp16.h>
#include <stdint.h>

// Hopfield layer via warp-level fp16 mma.sync (sm_100 target, no tcgen05).
// R17: both Hopfield steps fused in ONE kernel. Inner tile loop is R13's
// verbatim (2-buffer KV ring, half-split tiles, C folded into Q, f16x2
// packing, ones-column-MMA row sums, non-volatile mma). Between steps the
// step-2 Q fragments are rebuilt in registers from step-1 accumulators
// (C-frag layout == A-frag layout, inv = C/l folded per row); the KV ring
// is drained and restarted. Q (fp32 R) converted in-prologue.

#define DM 512
#define QT 256
#define ST 64
#define THREADS 256

// dynamic smem: 2 KV buffers (8KB each) + Q staging (32KB, prologue only)
#define KBUF(i)  ((uint32_t)(i) * 8192u)
#define QB0 16384
#define SMEM_TOTAL 49152

#define NELEM (2u * 2048u * 512u)
__device__ __half gYh[NELEM];

static __device__ __forceinline__ uint32_t s2u(const void* p) {
    uint32_t a;
    asm("{ .reg .u64 t; cvta.to.shared.u64 t, %1; cvt.u32.u64 %0, t; }"
        : "=r"(a) : "l"(p));
    return a;
}
static __device__ __forceinline__ uint32_t off(int row, int chunk) {
    return (uint32_t)(row * 128 + ((chunk ^ (row & 7)) << 4));
}
static __device__ __forceinline__ float ex2f_(float x) {
    float r; asm("ex2.approx.ftz.f32 %0, %1;" : "=f"(r) : "f"(x)); return r;
}
static __device__ __forceinline__ uint32_t packh2(float lo, float hi) {
    uint32_t r;
    asm("cvt.rn.f16x2.f32 %0, %1, %2;" : "=r"(r) : "f"(hi), "f"(lo));
    return r;
}

// pure register op: not volatile, lets ptxas schedule freely
static __device__ __forceinline__ void mma_f16(float c[4], const uint32_t a[4],
                                               const uint32_t b[2]) {
    asm("mma.sync.aligned.m16n8k16.row.col.f32.f16.f16.f32 "
        "{%0,%1,%2,%3}, {%4,%5,%6,%7}, {%8,%9}, {%0,%1,%2,%3};"
        : "+f"(c[0]), "+f"(c[1]), "+f"(c[2]), "+f"(c[3])
        : "r"(a[0]), "r"(a[1]), "r"(a[2]), "r"(a[3]), "r"(b[0]), "r"(b[1]));
}
#define LDSM4(r, a) \
    asm volatile("ldmatrix.sync.aligned.m8n8.x4.shared.b16 {%0,%1,%2,%3}, [%4];" \
        : "=r"((r)[0]), "=r"((r)[1]), "=r"((r)[2]), "=r"((r)[3]) : "r"(a))
#define LDSM4T(r, a) \
    asm volatile("ldmatrix.sync.aligned.m8n8.x4.trans.shared.b16 {%0,%1,%2,%3}, [%4];" \
        : "=r"((r)[0]), "=r"((r)[1]), "=r"((r)[2]), "=r"((r)[3]) : "r"(a))
#define CPA(dst, src) \
    asm volatile("cp.async.cg.shared.global [%0], [%1], 16;" :: "r"(dst), "l"(src))
#define CPC() asm volatile("cp.async.commit_group;" ::: "memory")
#define CPW(n) asm volatile("cp.async.wait_group %0;" :: "n"(n) : "memory")
#define STS128(a, r0, r1, r2, r3) \
    asm volatile("st.shared.v4.b32 [%0], {%1,%2,%3,%4};" \
        :: "r"(a), "r"(r0), "r"(r1), "r"(r2), "r"(r3) : "memory")

__global__ void tohalf(const float4* __restrict__ src, uint2* __restrict__ dst, int n4)
{
    int i = blockIdx.x * blockDim.x + threadIdx.x;
    if (i < n4) {
        float4 x = src[i];
        dst[i] = make_uint2(packh2(x.x, x.y), packh2(x.z, x.w));
    }
}

__global__ __launch_bounds__(THREADS, 1)
void hopfield_fused(const float* __restrict__ Rm, const __half* __restrict__ Km,
                    float* __restrict__ outF, int L, int S, float C)
{
    extern __shared__ __align__(16) uint8_t smem[];
    const uint32_t sb = s2u(smem);
    const uint32_t qB = sb + QB0;

    const int tid = threadIdx.x;
    const int wid = tid >> 5;
    const int lane = tid & 31;
    const int h = blockIdx.y, b = blockIdx.z;
    const int NT = S / ST;   // 32

    const uint32_t ones2[2] = { 0x3C003C00u, 0x3C003C00u };   // fp16 {1,1}
    const __half* kg = Km + (size_t)b * S * DM + h * 64;

    // ---- prologue: convert fp32 R tile (C folded) into swizzled fp16 smem ----
    {
        const float* qg = Rm + ((size_t)b * L + (size_t)blockIdx.x * QT) * DM + h * 64;
        int c8 = tid & 7, r0 = tid >> 3;   // 0..31
#pragma unroll
        for (int i = 0; i < 8; i++) {
            int row = r0 + i * 32;         // 0..255
            const float4* p = (const float4*)(qg + (size_t)row * DM + c8 * 8);
            float4 a = p[0], bb = p[1];
            STS128(qB + off(row, c8),
                   packh2(a.x * C, a.y * C), packh2(a.z * C, a.w * C),
                   packh2(bb.x * C, bb.y * C), packh2(bb.z * C, bb.w * C));
        }
    }
    __syncthreads();

    // per-warp A fragments: 2 row-tiles of 16x64; warp w owns rows 32w..32w+31
    uint32_t qf[2][4][4];
#pragma unroll
    for (int rt = 0; rt < 2; rt++) {
        int gr = 32 * wid + 16 * rt + (lane & 15);
#pragma unroll
        for (int t = 0; t < 4; t++) {
            int ch = 2 * t + (lane >> 4);
            LDSM4(qf[rt][t], qB + off(gr, ch));
        }
    }

    float oacc[2][8][4];
    float lacc[2][4];

#pragma unroll 1
    for (int step = 0; step < 2; step++) {
#pragma unroll
        for (int rt = 0; rt < 2; rt++) {
#pragma unroll
            for (int j = 0; j < 8; j++)
#pragma unroll
                for (int i = 0; i < 4; i++) oacc[rt][j][i] = 0.f;
#pragma unroll
            for (int i = 0; i < 4; i++) lacc[rt][i] = 0.f;
        }

        // prefetch tiles 0, 1
        {
            int c = tid & 7, r0 = tid >> 3;
#pragma unroll
            for (int pf = 0; pf < 2; pf++) {
                uint32_t bh = sb + KBUF(pf);
                const char* hs = (const char*)(kg + (size_t)pf * ST * DM);
#pragma unroll
                for (int i = 0; i < 2; i++) {
                    int row = r0 + i * 32;
                    CPA(bh + off(row, c), hs + (size_t)row * DM * 2 + c * 16);
                }
                CPC();
            }
        }

#pragma unroll 1
        for (int t = 0; t < NT; t++) {
            CPW(1);
            __syncthreads();
            const uint32_t kb = sb + KBUF(t & 1);

            // ---- process tile in two 32-key halves (R13 verbatim) ----
#pragma unroll
            for (int half = 0; half < 2; half++) {
                float sc[2][4][4];
#pragma unroll
                for (int rt = 0; rt < 2; rt++)
#pragma unroll
                    for (int j = 0; j < 4; j++)
#pragma unroll
                        for (int i = 0; i < 4; i++) sc[rt][j][i] = 0.f;

#pragma unroll
                for (int j = 0; j < 4; j++) {
                    int row = 32 * half + 8 * j + (lane & 7);
                    uint32_t bh[8];
                    LDSM4(bh + 0, kb + off(row, (lane >> 3)));
                    LDSM4(bh + 4, kb + off(row, 4 + (lane >> 3)));
#pragma unroll
                    for (int t4 = 0; t4 < 4; t4++)
#pragma unroll
                        for (int rt = 0; rt < 2; rt++)
                            mma_f16(sc[rt][j], qf[rt][t4], bh + 2 * t4);
                }

                uint32_t ph[2][2][4];
#pragma unroll
                for (int rt = 0; rt < 2; rt++) {
#pragma unroll
                    for (int kt = 0; kt < 2; kt++) {
                        ph[rt][kt][0] = packh2(ex2f_(sc[rt][2 * kt][0]),
                                               ex2f_(sc[rt][2 * kt][1]));
                        ph[rt][kt][1] = packh2(ex2f_(sc[rt][2 * kt][2]),
                                               ex2f_(sc[rt][2 * kt][3]));
                        ph[rt][kt][2] = packh2(ex2f_(sc[rt][2 * kt + 1][0]),
                                               ex2f_(sc[rt][2 * kt + 1][1]));
                        ph[rt][kt][3] = packh2(ex2f_(sc[rt][2 * kt + 1][2]),
                                               ex2f_(sc[rt][2 * kt + 1][3]));
                    }
                }

#pragma unroll
                for (int kt = 0; kt < 2; kt++) {
                    int row = 32 * half + 16 * kt + (lane & 7) + (lane & 8);
#pragma unroll
                    for (int jp = 0; jp < 4; jp++) {
                        int ch = 2 * jp + (lane >> 4);
                        uint32_t vh[4];
                        LDSM4T(vh, kb + off(row, ch));
#pragma unroll
                        for (int rt = 0; rt < 2; rt++) {
                            mma_f16(oacc[rt][2 * jp],     ph[rt][kt], vh + 0);
                            mma_f16(oacc[rt][2 * jp + 1], ph[rt][kt], vh + 2);
                        }
                    }
#pragma unroll
                    for (int rt = 0; rt < 2; rt++)
                        mma_f16(lacc[rt], ph[rt][kt], ones2);
                }
            }
            __syncthreads();

            // prefetch tile t+2 into the buffer just freed
            if (t + 2 < NT) {
                int c = tid & 7, r0 = tid >> 3;
                const char* hs = (const char*)(kg + (size_t)(t + 2) * ST * DM);
#pragma unroll
                for (int i = 0; i < 2; i++) {
                    int row = r0 + i * 32;
                    CPA(kb + off(row, c), hs + (size_t)row * DM * 2 + c * 16);
                }
            }
            CPC();
        }

        if (step == 0) {
            // rebuild step-2 Q fragments in registers: C-frag == A-frag layout,
            // normalization and softmax scale folded per row (inv = C / l)
#pragma unroll
            for (int rt = 0; rt < 2; rt++) {
                float inv0 = C / lacc[rt][0];
                float inv1 = C / lacc[rt][2];
#pragma unroll
                for (int t4 = 0; t4 < 4; t4++) {
                    qf[rt][t4][0] = packh2(oacc[rt][2 * t4][0] * inv0,
                                           oacc[rt][2 * t4][1] * inv0);
                    qf[rt][t4][1] = packh2(oacc[rt][2 * t4][2] * inv1,
                                           oacc[rt][2 * t4][3] * inv1);
                    qf[rt][t4][2] = packh2(oacc[rt][2 * t4 + 1][0] * inv0,
                                           oacc[rt][2 * t4 + 1][1] * inv0);
                    qf[rt][t4][3] = packh2(oacc[rt][2 * t4 + 1][2] * inv1,
                                           oacc[rt][2 * t4 + 1][3] * inv1);
                }
            }
            // drain the KV ring before restarting it for step 1
            CPW(0);
            __syncthreads();
        }
    }

    // ---- final normalize + fp32 store ----
    const int r = lane >> 2, cb = (lane & 3) * 2;
#pragma unroll
    for (int rt = 0; rt < 2; rt++) {
        float inv0 = 1.f / lacc[rt][0];
        float inv1 = 1.f / lacc[rt][2];
        size_t base = ((size_t)b * L + (size_t)blockIdx.x * QT + 32 * wid + 16 * rt) * DM
                    + h * 64;
#pragma unroll
        for (int j = 0; j < 8; j++) {
            *(float2*)(outF + base + (size_t)r * DM + 8 * j + cb) =
                make_float2(oacc[rt][j][0] * inv0, oacc[rt][j][1] * inv0);
            *(float2*)(outF + base + (size_t)(r + 8) * DM + 8 * j + cb) =
                make_float2(oacc[rt][j][2] * inv1, oacc[rt][j][3] * inv1);
        }
    }
}

extern "C" void kernel_launch(void* const* d_in, const int* in_sizes, int n_in,
                              void* d_out, int out_size)
{
    const float* R = (const float*)d_in[0];
    const float* Y = (const float*)d_in[1];
    float* out = (float*)d_out;

    const int B = 2, H = 8;
    const int L = in_sizes[0] / (B * DM);   // 2048
    const int S = in_sizes[1] / (B * DM);   // 2048
    const float C = 0.125f * 1.4426950408889634f;   // scale * log2(e)

    __half* Yh;
    cudaGetSymbolAddress((void**)&Yh, gYh);

    cudaFuncSetAttribute(hopfield_fused, cudaFuncAttributeMaxDynamicSharedMemorySize,
                         SMEM_TOTAL);

    const int n4 = (int)(NELEM / 4);
    tohalf<<<(n4 + 255) / 256, 256>>>((const float4*)Y, (uint2*)Yh, n4);

    dim3 grid(L / QT, H, B);
    dim3 block(THREADS);
    hopfield_fused<<<grid, block, SMEM_TOTAL>>>(R, Yh, out, L, S, C);
}